// round 14
// baseline (speedup 1.0000x reference)
#include <cuda_runtime.h>
#include <cuda_fp16.h>

#define GW 512
#define NNODE (GW * GW)
#define HID 64
#define NU_C 0.01f
#define TPB 256
#define BND_NODES 4080

typedef unsigned long long u64;

// Scratch: pass-1 gradients
__device__ float4 g_grad[NNODE];   // (gu0, gu1, gv0, gv1)
__device__ float2 g_gp[NNODE];     // (gp0, gp1)

// ---------------- packed helpers ----------------
__device__ __forceinline__ u64 F2(float lo, float hi) {
    u64 r; asm("mov.b64 %0,{%1,%2};" : "=l"(r) : "f"(lo), "f"(hi)); return r;
}
__device__ __forceinline__ u64 BC(float x) { return F2(x, x); }
__device__ __forceinline__ void UNPK(u64 v, float& lo, float& hi) {
    asm("mov.b64 {%0,%1},%2;" : "=f"(lo), "=f"(hi) : "l"(v));
}
__device__ __forceinline__ u64 FFMA2(u64 a, u64 b, u64 c) {
    u64 d; asm("fma.rn.f32x2 %0,%1,%2,%3;" : "=l"(d) : "l"(a), "l"(b), "l"(c)); return d;
}
__device__ __forceinline__ float tanhfast(float x) {
    float y; asm("tanh.approx.f32 %0, %1;" : "=f"(y) : "f"(x)); return y;
}
__device__ __forceinline__ __half2 tanh2(__half2 x) {
    unsigned xi = *reinterpret_cast<unsigned*>(&x), yi;
    asm("tanh.approx.f16x2 %0, %1;" : "=r"(yi) : "r"(xi));
    return *reinterpret_cast<__half2*>(&yi);
}
__device__ __forceinline__ __half2 h2bc(float x) {
    return __half2half2(__float2half_rn(x));
}
__device__ __forceinline__ __half2 cvt2h(u64 v) {
    unsigned r;
    asm("{.reg .f32 lo,hi; mov.b64 {lo,hi},%1; cvt.rn.f16x2.f32 %0, hi, lo;}"
        : "=r"(r) : "l"(v));
    return *reinterpret_cast<__half2*>(&r);
}
__device__ __forceinline__ __half2 u2h(unsigned r) {
    return *reinterpret_cast<__half2*>(&r);
}

// deg-3 odd poly tanh (pass2 only; errors damped by NU=0.01) — validated R8-R12
struct PolyC { __half2 A, B, C, D, LO, HI; };
__device__ __forceinline__ __half2 tanh_poly3(__half2 x, const PolyC& pc) {
    __half2 xc = __hmin2(__hmax2(x, pc.LO), pc.HI);
    __half2 y = __hmul2(xc, xc);
    __half2 p = __hfma2(pc.D, y, pc.C);
    p = __hfma2(p, y, pc.B);
    p = __hfma2(p, y, pc.A);
    return __hmul2(p, xc);
}
__device__ __forceinline__ PolyC make_poly() {
    PolyC pc;
    pc.A = h2bc(0.960139f);
    pc.B = h2bc(-0.187239f);
    pc.C = h2bc(0.0183402f);
    pc.D = h2bc(-0.00058827f);
    pc.LO = h2bc(-4.0f);
    pc.HI = h2bc(4.0f);
    return pc;
}

// ---------------- shared weights (16B-packed) ----------------
struct SW {
    ulonglong2 w02[HID];
    ulonglong2 cdi[HID];
    ulonglong2 w2cb[HID];
    ulonglong2 w13[HID];
    ulonglong2 adb[HID];
    uint2 w2c[HID];
    uint4 whq[HID];
    uint2 cdhq[HID];
};

__device__ __forceinline__ void load_weights(SW* s,
                                             const float* __restrict__ W1,
                                             const float* __restrict__ b1,
                                             const float* __restrict__ W2) {
    const float hx = 1.0f / 511.0f;
    const float hy = 1.0f / 511.0f;
    for (int k = threadIdx.x; k < HID; k += blockDim.x) {
        float w0 = W1[0 * HID + k], w1 = W1[1 * HID + k], w2 = W1[2 * HID + k];
        float w3 = W1[3 * HID + k], w4 = W1[4 * HID + k], w5 = W1[5 * HID + k];
        float b = b1[k];
        s->w02[k] = make_ulonglong2(BC(w0), BC(w2));
        s->w13[k] = make_ulonglong2(BC(w1), BC(w3));
        float a0l = b - hx * w4, a0r = b + hx * w4;
        float a1d = b - hy * w5, a1u = b + hy * w5;
        s->adb[k] = make_ulonglong2(F2(a0l, a0r), F2(a1d, a1u));
        float c4 = 4.0f * w1 + 4.0f * w3;   // interior: degi = 4, dj = 4
        float cL = a0l + c4, cR = a0r + c4, cD = a1d + c4, cU = a1u + c4;
        s->cdi[k] = make_ulonglong2(F2(cL, cR), F2(cD, cU));
        __half2 h0 = __floats2half2_rn(cL, cR), h1 = __floats2half2_rn(cD, cU);
        s->cdhq[k] = make_uint2(*reinterpret_cast<unsigned*>(&h0),
                                *reinterpret_cast<unsigned*>(&h1));
        float w20 = W2[2 * k + 0], w21 = W2[2 * k + 1];
        s->w2cb[k] = make_ulonglong2(BC(w20), BC(w21));
        __half2 h20 = h2bc(w20), h21 = h2bc(w21);
        unsigned u20 = *reinterpret_cast<unsigned*>(&h20);
        unsigned u21 = *reinterpret_cast<unsigned*>(&h21);
        s->w2c[k] = make_uint2(u20, u21);
        __half2 hw0 = h2bc(w0), hw2 = h2bc(w2);
        s->whq[k] = make_uint4(*reinterpret_cast<unsigned*>(&hw0),
                               *reinterpret_cast<unsigned*>(&hw2), u20, u21);
    }
    __syncthreads();
}

__device__ __forceinline__ float degat(int c, int r) {
    return (float)((c > 0) + (c < GW - 1) + (r > 0) + (r < GW - 1));
}

__device__ __forceinline__ bool bmap(int t, int& col, int& row) {
    if (t < 1024) { row = t >> 9; col = t & (GW - 1); return true; }
    if (t < 2048) { int u = t - 1024; row = 510 + (u >> 9); col = u & (GW - 1); return true; }
    if (t < 3064) { int u = t - 2048; col = u & 1; row = 2 + (u >> 1); return true; }
    if (t < BND_NODES) { int u = t - 3064; col = 510 + (u & 1); row = 2 + (u >> 1); return true; }
    return false;
}

// ===========================================================================
// Device bodies (R12-proven arithmetic)
// ===========================================================================

__device__ __forceinline__ void p1_interior(const SW& s, const float* __restrict__ fields,
                                            const float* __restrict__ b2, int i) {
    int col = i & (GW - 1);
    if (col < 2 || col > GW - 3) return;

    u64 si2[3], sj2[3][2];
#pragma unroll
    for (int f = 0; f < 3; f++) {
        si2[f] = BC(fields[3 * i + f]);
        sj2[f][0] = F2(fields[3 * (i - 1) + f], fields[3 * (i + 1) + f]);
        sj2[f][1] = F2(fields[3 * (i - GW) + f], fields[3 * (i + GW) + f]);
    }
    u64 acc2[3][2][2];
#pragma unroll
    for (int f = 0; f < 3; f++)
#pragma unroll
        for (int c = 0; c < 2; c++) { acc2[f][c][0] = BC(0.f); acc2[f][c][1] = BC(0.f); }

#pragma unroll 8
    for (int k = 0; k < HID; k++) {
        ulonglong2 wp = s.w02[k];
        ulonglong2 cd = s.cdi[k];
        ulonglong2 wc = s.w2cb[k];
#pragma unroll
        for (int f = 0; f < 3; f++) {
            u64 a0 = FFMA2(sj2[f][0], wp.y, FFMA2(si2[f], wp.x, cd.x));
            float x0, x1; UNPK(a0, x0, x1);
            u64 t0 = F2(tanhfast(x0), tanhfast(x1));
            acc2[f][0][0] = FFMA2(t0, wc.x, acc2[f][0][0]);
            acc2[f][1][0] = FFMA2(t0, wc.y, acc2[f][1][0]);
            u64 a1 = FFMA2(sj2[f][1], wp.y, FFMA2(si2[f], wp.x, cd.y));
            UNPK(a1, x0, x1);
            u64 t1 = F2(tanhfast(x0), tanhfast(x1));
            acc2[f][0][1] = FFMA2(t1, wc.x, acc2[f][0][1]);
            acc2[f][1][1] = FFMA2(t1, wc.y, acc2[f][1][1]);
        }
    }
    const float inv = 0.25f;
    float b20 = b2[0], b21 = b2[1];
    float facc[3][2];
#pragma unroll
    for (int f = 0; f < 3; f++)
#pragma unroll
        for (int c = 0; c < 2; c++) {
            float x0, x1, x2, x3;
            UNPK(acc2[f][c][0], x0, x1);
            UNPK(acc2[f][c][1], x2, x3);
            facc[f][c] = (x0 + x1) + (x2 + x3);
        }
    float4 gr;
    gr.x = fmaf(facc[0][0], inv, b20);
    gr.y = fmaf(facc[0][1], inv, b21);
    gr.z = fmaf(facc[1][0], inv, b20);
    gr.w = fmaf(facc[1][1], inv, b21);
    g_grad[i] = gr;
    float2 gp;
    gp.x = fmaf(facc[2][0], inv, b20);
    gp.y = fmaf(facc[2][1], inv, b21);
    g_gp[i] = gp;
}

__device__ __forceinline__ void p1_boundary(const SW& s, const float* __restrict__ fields,
                                            const float* __restrict__ b2,
                                            int t, int brlo, int brhi) {
    const __half2 z2 = __floats2half2_rn(0.f, 0.f);
    int col, row;
    if (!bmap(t, col, row)) return;
    if (row < brlo || row > brhi) return;
    int i = row * GW + col;
    bool vL = col > 0, vR = col < GW - 1, vD = row > 0, vU = row < GW - 1;
    float mk[4] = {vL ? 1.f : 0.f, vR ? 1.f : 0.f, vD ? 1.f : 0.f, vU ? 1.f : 0.f};
    int jn[4] = {vL ? i - 1 : i, vR ? i + 1 : i, vD ? i - GW : i, vU ? i + GW : i};
    float degi = mk[0] + mk[1] + mk[2] + mk[3];
    float dj[4] = {degat(col - 1, row), degat(col + 1, row),
                   degat(col, row - 1), degat(col, row + 1)};
    u64 dj2[2] = {F2(dj[0], dj[1]), F2(dj[2], dj[3])};
    u64 degi2 = BC(degi);

    u64 si2[3], sj2[3][2];
#pragma unroll
    for (int f = 0; f < 3; f++) {
        si2[f] = BC(fields[3 * i + f]);
        sj2[f][0] = F2(fields[3 * jn[0] + f], fields[3 * jn[1] + f]);
        sj2[f][1] = F2(fields[3 * jn[2] + f], fields[3 * jn[3] + f]);
    }
    __half2 ah[3][2][2];
    float facc[3][2];
#pragma unroll
    for (int f = 0; f < 3; f++)
#pragma unroll
        for (int c = 0; c < 2; c++) {
            ah[f][c][0] = z2; ah[f][c][1] = z2; facc[f][c] = 0.f;
        }

    for (int kb = 0; kb < HID; kb += 8) {
#pragma unroll
        for (int kk = 0; kk < 8; kk++) {
            int k = kb + kk;
            ulonglong2 wp = s.w02[k];
            ulonglong2 w13 = s.w13[k];
            ulonglong2 ad = s.adb[k];
            uint2 wc = s.w2c[k];
            __half2 w20h = u2h(wc.x), w21h = u2h(wc.y);
            u64 cd0 = FFMA2(dj2[0], w13.y, FFMA2(degi2, w13.x, ad.x));
            u64 cd1 = FFMA2(dj2[1], w13.y, FFMA2(degi2, w13.x, ad.y));
#pragma unroll
            for (int f = 0; f < 3; f++) {
                u64 a0 = FFMA2(sj2[f][0], wp.y, FFMA2(si2[f], wp.x, cd0));
                __half2 t0 = tanh2(cvt2h(a0));
                ah[f][0][0] = __hfma2(t0, w20h, ah[f][0][0]);
                ah[f][1][0] = __hfma2(t0, w21h, ah[f][1][0]);
                u64 a1 = FFMA2(sj2[f][1], wp.y, FFMA2(si2[f], wp.x, cd1));
                __half2 t1 = tanh2(cvt2h(a1));
                ah[f][0][1] = __hfma2(t1, w20h, ah[f][0][1]);
                ah[f][1][1] = __hfma2(t1, w21h, ah[f][1][1]);
            }
        }
#pragma unroll
        for (int f = 0; f < 3; f++)
#pragma unroll
            for (int c = 0; c < 2; c++)
#pragma unroll
                for (int dp = 0; dp < 2; dp++) {
                    float2 v = __half22float2(ah[f][c][dp]);
                    facc[f][c] = fmaf(mk[2 * dp], v.x,
                                 fmaf(mk[2 * dp + 1], v.y, facc[f][c]));
                    ah[f][c][dp] = z2;
                }
    }

    float inv = 1.0f / degi;
    float b20 = b2[0], b21 = b2[1];
    float4 gr;
    gr.x = fmaf(facc[0][0], inv, b20);
    gr.y = fmaf(facc[0][1], inv, b21);
    gr.z = fmaf(facc[1][0], inv, b20);
    gr.w = fmaf(facc[1][1], inv, b21);
    g_grad[i] = gr;
    float2 gp;
    gp.x = fmaf(facc[2][0], inv, b20);
    gp.y = fmaf(facc[2][1], inv, b21);
    g_gp[i] = gp;
}

// M0 = # MUFU pairs in dpair0 (rest poly); M1 = # MUFU pairs in dpair1
template <int M0, int M1>
__device__ __forceinline__ void p2_interior(const SW& s, const PolyC& pc,
                                            const float* __restrict__ fields,
                                            const float* __restrict__ b2,
                                            float* __restrict__ out, int i) {
    int col = i & (GW - 1);
    if (col < 2 || col > GW - 3) return;
    const __half2 z2 = __floats2half2_rn(0.f, 0.f);

    float4 gri = g_grad[i];
    float4 gL = g_grad[i - 1], gR = g_grad[i + 1];
    float4 gD = g_grad[i - GW], gU = g_grad[i + GW];

    __half2 sih[4], sjh[4][2];
    sih[0] = h2bc(gri.x); sih[1] = h2bc(gri.y);
    sih[2] = h2bc(gri.z); sih[3] = h2bc(gri.w);
    sjh[0][0] = __floats2half2_rn(gL.x, gR.x);
    sjh[0][1] = __floats2half2_rn(gD.x, gU.x);
    sjh[1][0] = __floats2half2_rn(gL.y, gR.y);
    sjh[1][1] = __floats2half2_rn(gD.y, gU.y);
    sjh[2][0] = __floats2half2_rn(gL.z, gR.z);
    sjh[2][1] = __floats2half2_rn(gD.z, gU.z);
    sjh[3][0] = __floats2half2_rn(gL.w, gR.w);
    sjh[3][1] = __floats2half2_rn(gD.w, gU.w);

    __half2 ah[4][2];
    float facc[4] = {0, 0, 0, 0};
#pragma unroll
    for (int f = 0; f < 4; f++) { ah[f][0] = z2; ah[f][1] = z2; }

    for (int kb = 0; kb < HID; kb += 16) {
#pragma unroll
        for (int kk = 0; kk < 16; kk++) {
            int k = kb + kk;
            uint4 w = s.whq[k];
            uint2 c = s.cdhq[k];
            __half2 w0h = u2h(w.x), w2h = u2h(w.y);
            __half2 w20h = u2h(w.z), w21h = u2h(w.w);
            __half2 cdh0 = u2h(c.x), cdh1 = u2h(c.y);
#pragma unroll
            for (int f = 0; f < 4; f++) {
                __half2 wcl = (f & 1) ? w21h : w20h;
                __half2 b0 = __hfma2(sih[f], w0h, cdh0);
                __half2 a0 = __hfma2(sjh[f][0], w2h, b0);
                __half2 t0 = (f < M0) ? tanh2(a0) : tanh_poly3(a0, pc);
                ah[f][0] = __hfma2(t0, wcl, ah[f][0]);
                __half2 b1h = __hfma2(sih[f], w0h, cdh1);
                __half2 a1 = __hfma2(sjh[f][1], w2h, b1h);
                __half2 t1 = (f < M1) ? tanh2(a1) : tanh_poly3(a1, pc);
                ah[f][1] = __hfma2(t1, wcl, ah[f][1]);
            }
        }
#pragma unroll
        for (int f = 0; f < 4; f++) {
            float2 v0 = __half22float2(ah[f][0]);
            float2 v1 = __half22float2(ah[f][1]);
            facc[f] += (v0.x + v0.y) + (v1.x + v1.y);
            ah[f][0] = z2; ah[f][1] = z2;
        }
    }

    const float inv = 0.25f;
    float b20 = b2[0], b21 = b2[1];
    float gux0 = fmaf(facc[0], inv, b20);
    float guy1 = fmaf(facc[1], inv, b21);
    float gvx0 = fmaf(facc[2], inv, b20);
    float gvy1 = fmaf(facc[3], inv, b21);
    float lap_u = gux0 + guy1;
    float lap_v = gvx0 + gvy1;
    float u = fields[3 * i + 0];
    float v = fields[3 * i + 1];
    float2 gp = g_gp[i];
    out[3 * i + 0] = gri.x + gri.w;
    out[3 * i + 1] = u * gri.x + v * gri.y + gp.x - NU_C * lap_u;
    out[3 * i + 2] = u * gri.z + v * gri.w + gp.y - NU_C * lap_v;
}

__device__ __forceinline__ void p2_boundary(const SW& s, const float* __restrict__ fields,
                                            const float* __restrict__ b2,
                                            float* __restrict__ out,
                                            int t, int brlo, int brhi) {
    const __half2 z2 = __floats2half2_rn(0.f, 0.f);
    int col, row;
    if (!bmap(t, col, row)) return;
    if (row < brlo || row > brhi) return;
    int i = row * GW + col;
    bool vL = col > 0, vR = col < GW - 1, vD = row > 0, vU = row < GW - 1;
    float mk[4] = {vL ? 1.f : 0.f, vR ? 1.f : 0.f, vD ? 1.f : 0.f, vU ? 1.f : 0.f};
    int jn[4] = {vL ? i - 1 : i, vR ? i + 1 : i, vD ? i - GW : i, vU ? i + GW : i};
    float degi = mk[0] + mk[1] + mk[2] + mk[3];
    float dj[4] = {degat(col - 1, row), degat(col + 1, row),
                   degat(col, row - 1), degat(col, row + 1)};
    u64 dj2[2] = {F2(dj[0], dj[1]), F2(dj[2], dj[3])};
    u64 degi2 = BC(degi);

    float4 gri = g_grad[i];
    float4 grn[4];
#pragma unroll
    for (int d = 0; d < 4; d++) grn[d] = g_grad[jn[d]];

    __half2 sih[4], sjh[4][2];
    sih[0] = h2bc(gri.x); sih[1] = h2bc(gri.y);
    sih[2] = h2bc(gri.z); sih[3] = h2bc(gri.w);
    sjh[0][0] = __floats2half2_rn(grn[0].x, grn[1].x);
    sjh[0][1] = __floats2half2_rn(grn[2].x, grn[3].x);
    sjh[1][0] = __floats2half2_rn(grn[0].y, grn[1].y);
    sjh[1][1] = __floats2half2_rn(grn[2].y, grn[3].y);
    sjh[2][0] = __floats2half2_rn(grn[0].z, grn[1].z);
    sjh[2][1] = __floats2half2_rn(grn[2].z, grn[3].z);
    sjh[3][0] = __floats2half2_rn(grn[0].w, grn[1].w);
    sjh[3][1] = __floats2half2_rn(grn[2].w, grn[3].w);

    __half2 ah[4][2];
    float facc[4] = {0, 0, 0, 0};
#pragma unroll
    for (int f = 0; f < 4; f++) { ah[f][0] = z2; ah[f][1] = z2; }

    for (int kb = 0; kb < HID; kb += 8) {
#pragma unroll
        for (int kk = 0; kk < 8; kk++) {
            int k = kb + kk;
            uint4 w = s.whq[k];
            ulonglong2 w13 = s.w13[k];
            ulonglong2 ad = s.adb[k];
            __half2 w0h = u2h(w.x), w2h = u2h(w.y);
            __half2 w20h = u2h(w.z), w21h = u2h(w.w);
            __half2 cdh0 = cvt2h(FFMA2(dj2[0], w13.y, FFMA2(degi2, w13.x, ad.x)));
            __half2 cdh1 = cvt2h(FFMA2(dj2[1], w13.y, FFMA2(degi2, w13.x, ad.y)));
#pragma unroll
            for (int f = 0; f < 4; f++) {
                __half2 wcl = (f & 1) ? w21h : w20h;
                __half2 b0 = __hfma2(sih[f], w0h, cdh0);
                __half2 t0 = tanh2(__hfma2(sjh[f][0], w2h, b0));
                ah[f][0] = __hfma2(t0, wcl, ah[f][0]);
                __half2 b1h = __hfma2(sih[f], w0h, cdh1);
                __half2 t1 = tanh2(__hfma2(sjh[f][1], w2h, b1h));
                ah[f][1] = __hfma2(t1, wcl, ah[f][1]);
            }
        }
#pragma unroll
        for (int f = 0; f < 4; f++)
#pragma unroll
            for (int dp = 0; dp < 2; dp++) {
                float2 v = __half22float2(ah[f][dp]);
                facc[f] = fmaf(mk[2 * dp], v.x,
                          fmaf(mk[2 * dp + 1], v.y, facc[f]));
                ah[f][dp] = z2;
            }
    }

    float inv = 1.0f / degi;
    float b20 = b2[0], b21 = b2[1];
    float gux0 = fmaf(facc[0], inv, b20);
    float guy1 = fmaf(facc[1], inv, b21);
    float gvx0 = fmaf(facc[2], inv, b20);
    float gvy1 = fmaf(facc[3], inv, b21);
    float lap_u = gux0 + guy1;
    float lap_v = gvx0 + gvy1;
    float u = fields[3 * i + 0];
    float v = fields[3 * i + 1];
    float2 gp = g_gp[i];
    out[3 * i + 0] = gri.x + gri.w;
    out[3 * i + 1] = u * gri.x + v * gri.y + gp.x - NU_C * lap_u;
    out[3 * i + 2] = u * gri.z + v * gri.w + gp.y - NU_C * lap_v;
}

// ===========================================================================
// K1: pass1 top (interior rows 2..259; boundary rows 0..259)
// ===========================================================================
__global__ void __launch_bounds__(TPB)
k1_kernel(const float* __restrict__ fields,
          const float* __restrict__ W1, const float* __restrict__ b1,
          const float* __restrict__ W2, const float* __restrict__ b2) {
    __shared__ SW s;
    load_weights(&s, W1, b1, W2);
    int bid = blockIdx.x, tid = threadIdx.x;
    if (bid < 516)
        p1_interior(s, fields, b2, 2 * GW + bid * TPB + tid);
    else
        p1_boundary(s, fields, b2, (bid - 516) * TPB + tid, 0, 259);
}

// ===========================================================================
// K2: MIX — pass1 bottom (rows 260..509 int; bnd 260..511)
//        +  pass2 top (rows 2..257 int; bnd 0..257), roles interleaved
//     pass2 here uses 3-MUFU/5-poly so the combined MUFU/FMA load balances
// ===========================================================================
__global__ void __launch_bounds__(TPB)
k2_kernel(const float* __restrict__ fields,
          const float* __restrict__ W1, const float* __restrict__ b1,
          const float* __restrict__ W2, const float* __restrict__ b2,
          float* __restrict__ out) {
    __shared__ SW s;
    load_weights(&s, W1, b1, W2);
    const PolyC pc = make_poly();
    int bid = blockIdx.x, tid = threadIdx.x;

    if (bid < 1000) {
        int idx = bid >> 1;
        if (bid & 1)
            p1_interior(s, fields, b2, 260 * GW + idx * TPB + tid);
        else
            p2_interior<3, 0>(s, pc, fields, b2, out, 2 * GW + idx * TPB + tid);
    } else if (bid < 1012) {
        int idx = 500 + (bid - 1000);
        p2_interior<3, 0>(s, pc, fields, b2, out, 2 * GW + idx * TPB + tid);
    } else if (bid < 1028) {
        p1_boundary(s, fields, b2, (bid - 1012) * TPB + tid, 260, 511);
    } else {
        p2_boundary(s, fields, b2, out, (bid - 1028) * TPB + tid, 0, 257);
    }
}

// ===========================================================================
// K3: pass2 bottom (interior rows 258..509; boundary rows 258..511), 5/3 split
// ===========================================================================
__global__ void __launch_bounds__(TPB)
k3_kernel(const float* __restrict__ fields,
          const float* __restrict__ W1, const float* __restrict__ b1,
          const float* __restrict__ W2, const float* __restrict__ b2,
          float* __restrict__ out) {
    __shared__ SW s;
    load_weights(&s, W1, b1, W2);
    const PolyC pc = make_poly();
    int bid = blockIdx.x, tid = threadIdx.x;
    if (bid < 504)
        p2_interior<4, 1>(s, pc, fields, b2, out, 258 * GW + bid * TPB + tid);
    else
        p2_boundary(s, fields, b2, out, (bid - 504) * TPB + tid, 258, 511);
}

extern "C" void kernel_launch(void* const* d_in, const int* in_sizes, int n_in,
                              void* d_out, int out_size) {
    const float* fields = (const float*)d_in[0];
    const float* W1 = (const float*)d_in[3];
    const float* b1 = (const float*)d_in[4];
    const float* W2 = (const float*)d_in[5];
    const float* b2 = (const float*)d_in[6];
    float* out = (float*)d_out;

    k1_kernel<<<532, TPB>>>(fields, W1, b1, W2, b2);
    k2_kernel<<<1044, TPB>>>(fields, W1, b1, W2, b2, out);
    k3_kernel<<<520, TPB>>>(fields, W1, b1, W2, b2, out);
}

// round 15
// speedup vs baseline: 1.1683x; 1.1683x over previous
#include <cuda_runtime.h>
#include <cuda_fp16.h>

#define GW 512
#define NNODE (GW * GW)
#define HID 64
#define NU_C 0.01f

#define TPB 256
#define INT_BLOCKS (NNODE / TPB)      // 1024
#define BND_NODES 4080
#define BND_BLOCKS 16

typedef unsigned long long u64;

// Scratch: pass-1 gradients
__device__ float4 g_grad[NNODE];   // (gu0, gu1, gv0, gv1)
__device__ float2 g_gp[NNODE];     // (gp0, gp1)

// ---------------- packed helpers ----------------
__device__ __forceinline__ u64 F2(float lo, float hi) {
    u64 r; asm("mov.b64 %0,{%1,%2};" : "=l"(r) : "f"(lo), "f"(hi)); return r;
}
__device__ __forceinline__ u64 BC(float x) { return F2(x, x); }
__device__ __forceinline__ void UNPK(u64 v, float& lo, float& hi) {
    asm("mov.b64 {%0,%1},%2;" : "=f"(lo), "=f"(hi) : "l"(v));
}
__device__ __forceinline__ u64 FFMA2(u64 a, u64 b, u64 c) {
    u64 d; asm("fma.rn.f32x2 %0,%1,%2,%3;" : "=l"(d) : "l"(a), "l"(b), "l"(c)); return d;
}
__device__ __forceinline__ float tanhfast(float x) {
    float y; asm("tanh.approx.f32 %0, %1;" : "=f"(y) : "f"(x)); return y;
}
__device__ __forceinline__ __half2 tanh2(__half2 x) {
    unsigned xi = *reinterpret_cast<unsigned*>(&x), yi;
    asm("tanh.approx.f16x2 %0, %1;" : "=r"(yi) : "r"(xi));
    return *reinterpret_cast<__half2*>(&yi);
}
__device__ __forceinline__ __half2 h2bc(float x) {
    return __half2half2(__float2half_rn(x));
}
__device__ __forceinline__ __half2 cvt2h(u64 v) {
    unsigned r;
    asm("{.reg .f32 lo,hi; mov.b64 {lo,hi},%1; cvt.rn.f16x2.f32 %0, hi, lo;}"
        : "=r"(r) : "l"(v));
    return *reinterpret_cast<__half2*>(&r);
}
__device__ __forceinline__ __half2 u2h(unsigned r) {
    return *reinterpret_cast<__half2*>(&r);
}

// deg-3 odd poly tanh (pass2 only; errors damped by NU=0.01):
// t = xc*P(xc^2), xc = clamp(x, +-4) — error-validated (R8-R12)
struct PolyC { __half2 A, B, C, D, LO, HI; };
__device__ __forceinline__ __half2 tanh_poly3(__half2 x, const PolyC& pc) {
    __half2 xc = __hmin2(__hmax2(x, pc.LO), pc.HI);
    __half2 y = __hmul2(xc, xc);
    __half2 p = __hfma2(pc.D, y, pc.C);
    p = __hfma2(p, y, pc.B);
    p = __hfma2(p, y, pc.A);
    return __hmul2(p, xc);
}
__device__ __forceinline__ PolyC make_poly() {
    PolyC pc;
    pc.A = h2bc(0.960139f);
    pc.B = h2bc(-0.187239f);
    pc.C = h2bc(0.0183402f);
    pc.D = h2bc(-0.00058827f);
    pc.LO = h2bc(-4.0f);
    pc.HI = h2bc(4.0f);
    return pc;
}

// ---------------- shared weights (16B-packed) ----------------
struct SW {
    ulonglong2 w02[HID];   // (w0 bcast f32x2, w2 bcast f32x2)      pass1 args
    ulonglong2 cdi[HID];   // interior cd: (cd_dpair0, cd_dpair1)    pass1
    ulonglong2 w2cb[HID];  // (w20 bcast f32x2, w21 bcast f32x2)     pass1 f32 acc
    ulonglong2 w13[HID];   // (w1 bcast, w3 bcast)                  boundary path
    ulonglong2 adb[HID];   // (adb_dpair0, adb_dpair1)              boundary path
    uint2 w2c[HID];        // (w20 f16x2, w21 f16x2)                boundary/pass2
    uint4 whq[HID];        // (w0h, w2h, w20h, w21h)                pass2 args
    uint2 cdhq[HID];       // interior cd as half2: (cdh0, cdh1)    pass2
};

__device__ __forceinline__ void load_weights(SW* s,
                                             const float* __restrict__ W1,
                                             const float* __restrict__ b1,
                                             const float* __restrict__ W2) {
    const float hx = 1.0f / 511.0f;
    const float hy = 1.0f / 511.0f;
    for (int k = threadIdx.x; k < HID; k += blockDim.x) {
        float w0 = W1[0 * HID + k], w1 = W1[1 * HID + k], w2 = W1[2 * HID + k];
        float w3 = W1[3 * HID + k], w4 = W1[4 * HID + k], w5 = W1[5 * HID + k];
        float b = b1[k];
        s->w02[k] = make_ulonglong2(BC(w0), BC(w2));
        s->w13[k] = make_ulonglong2(BC(w1), BC(w3));
        float a0l = b - hx * w4, a0r = b + hx * w4;
        float a1d = b - hy * w5, a1u = b + hy * w5;
        s->adb[k] = make_ulonglong2(F2(a0l, a0r), F2(a1d, a1u));
        float c4 = 4.0f * w1 + 4.0f * w3;   // interior: degi = 4, dj = 4
        float cL = a0l + c4, cR = a0r + c4, cD = a1d + c4, cU = a1u + c4;
        s->cdi[k] = make_ulonglong2(F2(cL, cR), F2(cD, cU));
        __half2 h0 = __floats2half2_rn(cL, cR), h1 = __floats2half2_rn(cD, cU);
        s->cdhq[k] = make_uint2(*reinterpret_cast<unsigned*>(&h0),
                                *reinterpret_cast<unsigned*>(&h1));
        float w20 = W2[2 * k + 0], w21 = W2[2 * k + 1];
        s->w2cb[k] = make_ulonglong2(BC(w20), BC(w21));
        __half2 h20 = h2bc(w20), h21 = h2bc(w21);
        unsigned u20 = *reinterpret_cast<unsigned*>(&h20);
        unsigned u21 = *reinterpret_cast<unsigned*>(&h21);
        s->w2c[k] = make_uint2(u20, u21);
        __half2 hw0 = h2bc(w0), hw2 = h2bc(w2);
        s->whq[k] = make_uint4(*reinterpret_cast<unsigned*>(&hw0),
                               *reinterpret_cast<unsigned*>(&hw2), u20, u21);
    }
    __syncthreads();
}

__device__ __forceinline__ float degat(int c, int r) {
    return (float)((c > 0) + (c < GW - 1) + (r > 0) + (r < GW - 1));
}

// map t in [0, BND_NODES) to a node within 2 of the boundary
__device__ __forceinline__ bool bmap(int t, int& col, int& row) {
    if (t < 1024) { row = t >> 9; col = t & (GW - 1); return true; }
    if (t < 2048) { int u = t - 1024; row = 510 + (u >> 9); col = u & (GW - 1); return true; }
    if (t < 3064) { int u = t - 2048; col = u & 1; row = 2 + (u >> 1); return true; }
    if (t < BND_NODES) { int u = t - 3064; col = 510 + (u & 1); row = 2 + (u >> 1); return true; }
    return false;
}

// ---------------------------------------------------------------------------
// Pass 1: interior = full f32 (f32x2 args/acc, f32 MUFU tanh) — proven 48.5us;
//         boundary = f16 acc path
// ---------------------------------------------------------------------------
__global__ void __launch_bounds__(TPB)
pass1_kernel(const float* __restrict__ fields,
             const float* __restrict__ W1, const float* __restrict__ b1,
             const float* __restrict__ W2, const float* __restrict__ b2) {
    __shared__ SW s;
    load_weights(&s, W1, b1, W2);

    int i, col, row;
    float degi;
    float facc[3][2];

    if (blockIdx.x < INT_BLOCKS) {
        // ---------------- interior path (f32, no divergence) -------------
        i = blockIdx.x * blockDim.x + threadIdx.x;
        col = i & (GW - 1);
        row = i >> 9;
        if (col < 2 || col > GW - 3 || row < 2 || row > GW - 3) return;
        degi = 4.0f;

        u64 si2[3], sj2[3][2];
#pragma unroll
        for (int f = 0; f < 3; f++) {
            si2[f] = BC(fields[3 * i + f]);
            sj2[f][0] = F2(fields[3 * (i - 1) + f], fields[3 * (i + 1) + f]);
            sj2[f][1] = F2(fields[3 * (i - GW) + f], fields[3 * (i + GW) + f]);
        }
        u64 acc2[3][2][2];   // [field][comp][dpair]
#pragma unroll
        for (int f = 0; f < 3; f++)
#pragma unroll
            for (int c = 0; c < 2; c++) { acc2[f][c][0] = BC(0.f); acc2[f][c][1] = BC(0.f); }

#pragma unroll 8
        for (int k = 0; k < HID; k++) {
            ulonglong2 wp = s.w02[k];
            ulonglong2 cd = s.cdi[k];
            ulonglong2 wc = s.w2cb[k];
#pragma unroll
            for (int f = 0; f < 3; f++) {
                u64 a0 = FFMA2(sj2[f][0], wp.y, FFMA2(si2[f], wp.x, cd.x));
                float x0, x1; UNPK(a0, x0, x1);
                u64 t0 = F2(tanhfast(x0), tanhfast(x1));
                acc2[f][0][0] = FFMA2(t0, wc.x, acc2[f][0][0]);
                acc2[f][1][0] = FFMA2(t0, wc.y, acc2[f][1][0]);
                u64 a1 = FFMA2(sj2[f][1], wp.y, FFMA2(si2[f], wp.x, cd.y));
                UNPK(a1, x0, x1);
                u64 t1 = F2(tanhfast(x0), tanhfast(x1));
                acc2[f][0][1] = FFMA2(t1, wc.x, acc2[f][0][1]);
                acc2[f][1][1] = FFMA2(t1, wc.y, acc2[f][1][1]);
            }
        }
#pragma unroll
        for (int f = 0; f < 3; f++)
#pragma unroll
            for (int c = 0; c < 2; c++) {
                float x0, x1, x2, x3;
                UNPK(acc2[f][c][0], x0, x1);
                UNPK(acc2[f][c][1], x2, x3);
                facc[f][c] = (x0 + x1) + (x2 + x3);
            }
    } else {
        // ---------------- boundary path (f16 acc, masked flush) ----------
        const __half2 z2 = __floats2half2_rn(0.f, 0.f);
        int t = (blockIdx.x - INT_BLOCKS) * blockDim.x + threadIdx.x;
        if (!bmap(t, col, row)) return;
        i = row * GW + col;
        bool vL = col > 0, vR = col < GW - 1, vD = row > 0, vU = row < GW - 1;
        float mk[4] = {vL ? 1.f : 0.f, vR ? 1.f : 0.f, vD ? 1.f : 0.f, vU ? 1.f : 0.f};
        int jn[4] = {vL ? i - 1 : i, vR ? i + 1 : i, vD ? i - GW : i, vU ? i + GW : i};
        degi = mk[0] + mk[1] + mk[2] + mk[3];
        float dj[4] = {degat(col - 1, row), degat(col + 1, row),
                       degat(col, row - 1), degat(col, row + 1)};
        u64 dj2[2] = {F2(dj[0], dj[1]), F2(dj[2], dj[3])};
        u64 degi2 = BC(degi);

        u64 si2[3], sj2[3][2];
#pragma unroll
        for (int f = 0; f < 3; f++) {
            si2[f] = BC(fields[3 * i + f]);
            sj2[f][0] = F2(fields[3 * jn[0] + f], fields[3 * jn[1] + f]);
            sj2[f][1] = F2(fields[3 * jn[2] + f], fields[3 * jn[3] + f]);
        }
        __half2 ah[3][2][2];
#pragma unroll
        for (int f = 0; f < 3; f++)
#pragma unroll
            for (int c = 0; c < 2; c++) { ah[f][c][0] = z2; ah[f][c][1] = z2; }
#pragma unroll
        for (int f = 0; f < 3; f++)
#pragma unroll
            for (int c = 0; c < 2; c++) facc[f][c] = 0.f;

        for (int kb = 0; kb < HID; kb += 8) {
#pragma unroll
            for (int kk = 0; kk < 8; kk++) {
                int k = kb + kk;
                ulonglong2 wp = s.w02[k];
                ulonglong2 w13 = s.w13[k];
                ulonglong2 ad = s.adb[k];
                uint2 wc = s.w2c[k];
                __half2 w20h = u2h(wc.x), w21h = u2h(wc.y);
                u64 cd0 = FFMA2(dj2[0], w13.y, FFMA2(degi2, w13.x, ad.x));
                u64 cd1 = FFMA2(dj2[1], w13.y, FFMA2(degi2, w13.x, ad.y));
#pragma unroll
                for (int f = 0; f < 3; f++) {
                    u64 a0 = FFMA2(sj2[f][0], wp.y, FFMA2(si2[f], wp.x, cd0));
                    __half2 t0 = tanh2(cvt2h(a0));
                    ah[f][0][0] = __hfma2(t0, w20h, ah[f][0][0]);
                    ah[f][1][0] = __hfma2(t0, w21h, ah[f][1][0]);
                    u64 a1 = FFMA2(sj2[f][1], wp.y, FFMA2(si2[f], wp.x, cd1));
                    __half2 t1 = tanh2(cvt2h(a1));
                    ah[f][0][1] = __hfma2(t1, w20h, ah[f][0][1]);
                    ah[f][1][1] = __hfma2(t1, w21h, ah[f][1][1]);
                }
            }
#pragma unroll
            for (int f = 0; f < 3; f++)
#pragma unroll
                for (int c = 0; c < 2; c++) {
#pragma unroll
                    for (int dp = 0; dp < 2; dp++) {
                        float2 v = __half22float2(ah[f][c][dp]);
                        facc[f][c] = fmaf(mk[2 * dp], v.x,
                                     fmaf(mk[2 * dp + 1], v.y, facc[f][c]));
                        ah[f][c][dp] = z2;
                    }
                }
        }
    }

    float inv = 1.0f / degi;
    float b20 = b2[0], b21 = b2[1];
    float4 gr;
    gr.x = fmaf(facc[0][0], inv, b20);
    gr.y = fmaf(facc[0][1], inv, b21);
    gr.z = fmaf(facc[1][0], inv, b20);
    gr.w = fmaf(facc[1][1], inv, b21);
    g_grad[i] = gr;
    float2 gp;
    gp.x = fmaf(facc[2][0], inv, b20);
    gp.y = fmaf(facc[2][1], inv, b21);
    g_gp[i] = gp;
}

// ---------------------------------------------------------------------------
// Pass 2: hybrid tanh — 5 MUFU pairs + 3 deg-3-poly pairs per k (proven 49.6us)
// ---------------------------------------------------------------------------
__global__ void __launch_bounds__(TPB)
pass2_kernel(const float* __restrict__ fields,
             const float* __restrict__ W1, const float* __restrict__ b1,
             const float* __restrict__ W2, const float* __restrict__ b2,
             float* __restrict__ out) {
    __shared__ SW s;
    load_weights(&s, W1, b1, W2);

    const __half2 z2 = __floats2half2_rn(0.f, 0.f);
    const PolyC pc = make_poly();
    float facc[4] = {0, 0, 0, 0};
    int i, col, row;
    float degi;
    float4 gri;

    if (blockIdx.x < INT_BLOCKS) {
        i = blockIdx.x * blockDim.x + threadIdx.x;
        col = i & (GW - 1);
        row = i >> 9;
        if (col < 2 || col > GW - 3 || row < 2 || row > GW - 3) return;
        degi = 4.0f;

        gri = g_grad[i];
        float4 gL = g_grad[i - 1], gR = g_grad[i + 1];
        float4 gD = g_grad[i - GW], gU = g_grad[i + GW];

        __half2 sih[4], sjh[4][2];
        sih[0] = h2bc(gri.x); sih[1] = h2bc(gri.y);
        sih[2] = h2bc(gri.z); sih[3] = h2bc(gri.w);
        sjh[0][0] = __floats2half2_rn(gL.x, gR.x);
        sjh[0][1] = __floats2half2_rn(gD.x, gU.x);
        sjh[1][0] = __floats2half2_rn(gL.y, gR.y);
        sjh[1][1] = __floats2half2_rn(gD.y, gU.y);
        sjh[2][0] = __floats2half2_rn(gL.z, gR.z);
        sjh[2][1] = __floats2half2_rn(gD.z, gU.z);
        sjh[3][0] = __floats2half2_rn(gL.w, gR.w);
        sjh[3][1] = __floats2half2_rn(gD.w, gU.w);

        __half2 ah[4][2];
#pragma unroll
        for (int f = 0; f < 4; f++) { ah[f][0] = z2; ah[f][1] = z2; }

        for (int kb = 0; kb < HID; kb += 16) {
#pragma unroll
            for (int kk = 0; kk < 16; kk++) {
                int k = kb + kk;
                uint4 w = s.whq[k];
                uint2 c = s.cdhq[k];
                __half2 w0h = u2h(w.x), w2h = u2h(w.y);
                __half2 w20h = u2h(w.z), w21h = u2h(w.w);
                __half2 cdh0 = u2h(c.x), cdh1 = u2h(c.y);
#pragma unroll
                for (int f = 0; f < 4; f++) {
                    __half2 wcl = (f & 1) ? w21h : w20h;
                    __half2 b0 = __hfma2(sih[f], w0h, cdh0);
                    __half2 a0 = __hfma2(sjh[f][0], w2h, b0);
                    __half2 t0 = tanh2(a0);                      // MUFU (4 pairs)
                    ah[f][0] = __hfma2(t0, wcl, ah[f][0]);
                    __half2 b1h = __hfma2(sih[f], w0h, cdh1);
                    __half2 a1 = __hfma2(sjh[f][1], w2h, b1h);
                    __half2 t1 = (f == 0) ? tanh2(a1)            // MUFU (1 pair)
                                          : tanh_poly3(a1, pc);  // FMA  (3 pairs)
                    ah[f][1] = __hfma2(t1, wcl, ah[f][1]);
                }
            }
#pragma unroll
            for (int f = 0; f < 4; f++) {
                float2 v0 = __half22float2(ah[f][0]);
                float2 v1 = __half22float2(ah[f][1]);
                facc[f] += (v0.x + v0.y) + (v1.x + v1.y);
                ah[f][0] = z2; ah[f][1] = z2;
            }
        }
    } else {
        int t = (blockIdx.x - INT_BLOCKS) * blockDim.x + threadIdx.x;
        if (!bmap(t, col, row)) return;
        i = row * GW + col;
        bool vL = col > 0, vR = col < GW - 1, vD = row > 0, vU = row < GW - 1;
        float mk[4] = {vL ? 1.f : 0.f, vR ? 1.f : 0.f, vD ? 1.f : 0.f, vU ? 1.f : 0.f};
        int jn[4] = {vL ? i - 1 : i, vR ? i + 1 : i, vD ? i - GW : i, vU ? i + GW : i};
        degi = mk[0] + mk[1] + mk[2] + mk[3];
        float dj[4] = {degat(col - 1, row), degat(col + 1, row),
                       degat(col, row - 1), degat(col, row + 1)};
        u64 dj2[2] = {F2(dj[0], dj[1]), F2(dj[2], dj[3])};
        u64 degi2 = BC(degi);

        gri = g_grad[i];
        float4 grn[4];
#pragma unroll
        for (int d = 0; d < 4; d++) grn[d] = g_grad[jn[d]];

        __half2 sih[4], sjh[4][2];
        sih[0] = h2bc(gri.x); sih[1] = h2bc(gri.y);
        sih[2] = h2bc(gri.z); sih[3] = h2bc(gri.w);
        sjh[0][0] = __floats2half2_rn(grn[0].x, grn[1].x);
        sjh[0][1] = __floats2half2_rn(grn[2].x, grn[3].x);
        sjh[1][0] = __floats2half2_rn(grn[0].y, grn[1].y);
        sjh[1][1] = __floats2half2_rn(grn[2].y, grn[3].y);
        sjh[2][0] = __floats2half2_rn(grn[0].z, grn[1].z);
        sjh[2][1] = __floats2half2_rn(grn[2].z, grn[3].z);
        sjh[3][0] = __floats2half2_rn(grn[0].w, grn[1].w);
        sjh[3][1] = __floats2half2_rn(grn[2].w, grn[3].w);

        __half2 ah[4][2];
#pragma unroll
        for (int f = 0; f < 4; f++) { ah[f][0] = z2; ah[f][1] = z2; }

        for (int kb = 0; kb < HID; kb += 8) {
#pragma unroll
            for (int kk = 0; kk < 8; kk++) {
                int k = kb + kk;
                uint4 w = s.whq[k];
                ulonglong2 w13 = s.w13[k];
                ulonglong2 ad = s.adb[k];
                __half2 w0h = u2h(w.x), w2h = u2h(w.y);
                __half2 w20h = u2h(w.z), w21h = u2h(w.w);
                __half2 cdh0 = cvt2h(FFMA2(dj2[0], w13.y, FFMA2(degi2, w13.x, ad.x)));
                __half2 cdh1 = cvt2h(FFMA2(dj2[1], w13.y, FFMA2(degi2, w13.x, ad.y)));
#pragma unroll
                for (int f = 0; f < 4; f++) {
                    __half2 wcl = (f & 1) ? w21h : w20h;
                    __half2 b0 = __hfma2(sih[f], w0h, cdh0);
                    __half2 t0 = tanh2(__hfma2(sjh[f][0], w2h, b0));
                    ah[f][0] = __hfma2(t0, wcl, ah[f][0]);
                    __half2 b1h = __hfma2(sih[f], w0h, cdh1);
                    __half2 t1 = tanh2(__hfma2(sjh[f][1], w2h, b1h));
                    ah[f][1] = __hfma2(t1, wcl, ah[f][1]);
                }
            }
#pragma unroll
            for (int f = 0; f < 4; f++)
#pragma unroll
                for (int dp = 0; dp < 2; dp++) {
                    float2 v = __half22float2(ah[f][dp]);
                    facc[f] = fmaf(mk[2 * dp], v.x,
                              fmaf(mk[2 * dp + 1], v.y, facc[f]));
                    ah[f][dp] = z2;
                }
        }
    }

    float inv = 1.0f / degi;
    float b20 = b2[0], b21 = b2[1];
    float gux0 = fmaf(facc[0], inv, b20);
    float guy1 = fmaf(facc[1], inv, b21);
    float gvx0 = fmaf(facc[2], inv, b20);
    float gvy1 = fmaf(facc[3], inv, b21);

    float lap_u = gux0 + guy1;
    float lap_v = gvx0 + gvy1;

    float u = fields[3 * i + 0];
    float v = fields[3 * i + 1];
    float2 gp = g_gp[i];

    out[3 * i + 0] = gri.x + gri.w;
    out[3 * i + 1] = u * gri.x + v * gri.y + gp.x - NU_C * lap_u;
    out[3 * i + 2] = u * gri.z + v * gri.w + gp.y - NU_C * lap_v;
}

extern "C" void kernel_launch(void* const* d_in, const int* in_sizes, int n_in,
                              void* d_out, int out_size) {
    const float* fields = (const float*)d_in[0];
    const float* W1 = (const float*)d_in[3];
    const float* b1 = (const float*)d_in[4];
    const float* W2 = (const float*)d_in[5];
    const float* b2 = (const float*)d_in[6];
    float* out = (float*)d_out;

    dim3 grid(INT_BLOCKS + BND_BLOCKS), block(TPB);
    pass1_kernel<<<grid, block>>>(fields, W1, b1, W2, b2);
    pass2_kernel<<<grid, block>>>(fields, W1, b1, W2, b2, out);
}